// round 3
// baseline (speedup 1.0000x reference)
#include <cuda_runtime.h>

// SoftBoundDDM_RT: 4096 trials x 2000-step leaky-DDM recurrence + soft bounds.
// One block (128 thr) per trial; 16 timesteps per thread.
// Linear recurrence solved as a weighted prefix SUM:
//   e[T] = D^T * ( e0 + sum_{i<T} u[i] * D^-(i+1) ),  D = 0.99999
// (weights bounded by D^-2000 = 1.0202 -> perfectly conditioned).

constexpr int   N_T    = 2000;
constexpr int   CH     = 16;          // timesteps per thread
constexpr int   TPB    = 128;         // 125 active threads (125*16 = 2000)
constexpr int   ACTIVE = 125;
constexpr float DT     = 0.001f;
constexpr float LEAK   = 0.01f;
constexpr float TC     = 0.01f;       // TIME_CONSTANT
constexpr float DECAY  = 1.0f - LEAK * DT;             // 0.99999
constexpr float DINV   = 1.0f / DECAY;
constexpr float LN_D16 = -1.6000080001e-4f;            // 16 * ln(0.99999)
constexpr float SQVDT  = 0.03162277660168379332f;      // sqrt(VARIANCE*DT)

__device__ __forceinline__ float sigm(float x) {
    return __fdividef(1.0f, 1.0f + __expf(-x));
}

__global__ __launch_bounds__(TPB)
void ddm_kernel(const float* __restrict__ stim,
                const float* __restrict__ noise,
                const float* __restrict__ pa,
                const float* __restrict__ pz,
                const float* __restrict__ pg,
                const float* __restrict__ po,
                const float* __restrict__ pb,
                float* __restrict__ out,
                long long total_elems)      // n_trials * N_T
{
    const int trial = blockIdx.x;
    const int t     = threadIdx.x;
    const int lane  = t & 31;
    const int warp  = t >> 5;

    const float a    = __ldg(pa);
    const float z    = __ldg(pz);
    const float g    = __ldg(pg);
    const float off  = __ldg(po);
    const float beta = __ldg(pb);

    const float e0     = z * a;
    const float cstim  = g * DT;
    const float cconst = off * DT + LEAK * e0 * DT;

    const bool  active = (t < ACTIVE);
    const size_t base  = (size_t)trial * N_T + (size_t)t * CH;

    // thread-level decay powers: G = D^(16t), F = D^(-16t)
    const float G = __expf(LN_D16 * (float)t);
    const float F = __expf(-LN_D16 * (float)t);

    // ---- load 16 u-values, build local weighted prefix p[k] = sum u[j]*D^-(j+1)
    float p[CH];
    if (active) {
        const float4* sp = reinterpret_cast<const float4*>(stim  + base);
        const float4* np = reinterpret_cast<const float4*>(noise + base);
        float4 s[4], n[4];
        #pragma unroll
        for (int q = 0; q < 4; q++) s[q] = __ldcs(sp + q);
        #pragma unroll
        for (int q = 0; q < 4; q++) n[q] = __ldcs(np + q);

        float dw = 1.0f;          // becomes DINV^(k+1); constant-folded per unrolled iter
        float acc = 0.0f;
        #pragma unroll
        for (int k = 0; k < CH; k++) {
            const float sv = (&s[k >> 2].x)[k & 3];
            const float nv = (&n[k >> 2].x)[k & 3];
            const float u  = fmaf(cstim, sv, fmaf(SQVDT, nv, cconst));
            dw *= DINV;
            acc = fmaf(u, dw, acc);
            p[k] = acc;
        }
    } else {
        #pragma unroll
        for (int k = 0; k < CH; k++) p[k] = 0.0f;
    }

    // thread total (in global weighting)
    const float S = active ? F * p[CH - 1] : 0.0f;

    // ---- inclusive warp add-scan ----
    float si = S;
    #pragma unroll
    for (int d = 1; d < 32; d <<= 1) {
        const float o = __shfl_up_sync(0xffffffffu, si, d);
        if (lane >= d) si += o;
    }

    __shared__ float sT[TPB / 32];
    if (lane == 31) sT[warp] = si;
    __syncthreads();

    // exclusive prefix for this thread
    float E = si - S;
    #pragma unroll
    for (int w = 0; w < TPB / 32; w++)
        if (w < warp) E += sT[w];

    if (!active) return;

    // ---- outputs ----
    const float basev = e0 + E;               // e0 + weighted sum of earlier threads
    const float nba   = -beta * a;
    const float tbase = (float)(t * CH) * TC;

    float dvv[CH], h1v[CH], h0v[CH];
    float dpow = 1.0f;                        // D^k, constant-folded per iter
    #pragma unroll
    for (int k = 0; k < CH; k++) {
        const float pprev = (k == 0) ? 0.0f : p[k - 1];
        const float inner = fmaf(F, pprev, basev);
        const float e     = G * (dpow * inner);           // evidence at T = 16t+k
        const float urg   = tbase + (float)k * TC;
        const float dv    = fmaf(urg, e - e0, e0);
        dvv[k] = dv;
        h1v[k] = sigm(fmaf(beta, dv, nba));               // sigmoid(beta*(dv-a))
        h0v[k] = sigm(-beta * dv);                        // sigmoid(-beta*dv)
        dpow  *= DECAY;
    }

    float* dvout = out + base;
    float* h1out = out + (size_t)total_elems + base;
    float* h0out = out + 2 * (size_t)total_elems + base;
    #pragma unroll
    for (int q = 0; q < 4; q++) {
        __stcs(reinterpret_cast<float4*>(dvout) + q,
               make_float4(dvv[q*4], dvv[q*4+1], dvv[q*4+2], dvv[q*4+3]));
        __stcs(reinterpret_cast<float4*>(h1out) + q,
               make_float4(h1v[q*4], h1v[q*4+1], h1v[q*4+2], h1v[q*4+3]));
        __stcs(reinterpret_cast<float4*>(h0out) + q,
               make_float4(h0v[q*4], h0v[q*4+1], h0v[q*4+2], h0v[q*4+3]));
    }
}

extern "C" void kernel_launch(void* const* d_in, const int* in_sizes, int n_in,
                              void* d_out, int out_size)
{
    const float* stim  = (const float*)d_in[0];
    const float* noise = (const float*)d_in[1];
    const float* pa    = (const float*)d_in[2];
    const float* pz    = (const float*)d_in[3];
    const float* pg    = (const float*)d_in[4];
    const float* po    = (const float*)d_in[5];
    const float* pb    = (const float*)d_in[6];
    float* out = (float*)d_out;

    const long long total = in_sizes[0];          // n_trials * N_T
    const int n_trials = (int)(total / N_T);

    ddm_kernel<<<n_trials, TPB>>>(stim, noise, pa, pz, pg, po, pb, out, total);
}

// round 5
// speedup vs baseline: 1.0926x; 1.0926x over previous
#include <cuda_runtime.h>

// SoftBoundDDM_RT: 4096 trials x 2000-step leaky-DDM recurrence + soft bounds.
// Persistent single-wave layout: 2048 blocks x 128 threads, 2 trials per block,
// register-double-buffered loads pipeline trial i+1 behind trial i's compute.
// Linear recurrence solved as a weighted prefix SUM:
//   e[T] = D^T * ( e0 + sum_{i<T} u[i] * D^-(i+1) ),  D = 0.99999.

constexpr int   N_T    = 2000;
constexpr int   CH     = 16;          // timesteps per thread
constexpr int   TPB    = 128;         // 125 active threads (125*16 = 2000)
constexpr int   ACTIVE = 125;
constexpr int   GTR    = 2;           // trials per block
constexpr float DT     = 0.001f;
constexpr float LEAK   = 0.01f;
constexpr float TC     = 0.01f;       // TIME_CONSTANT
constexpr float DECAY  = 1.0f - LEAK * DT;             // 0.99999
constexpr float DINV   = 1.0f / DECAY;
constexpr float LN_D16 = -1.6000080001e-4f;            // 16 * ln(0.99999)
constexpr float SQVDT  = 0.03162277660168379332f;      // sqrt(VARIANCE*DT)

// D^k for k = 0..15, compile-time constants (immediates in SASS)
__device__ __constant__ float DPOW[CH] = {
    1.0f,
    0.99999f,
    0.9999800001f,
    0.9999700003f,
    0.9999600006f,
    0.9999500010f,
    0.9999400015f,
    0.9999300021f,
    0.9999200028f,
    0.9999100036f,
    0.9999000045f,
    0.9998900055f,
    0.9998800066f,
    0.9998700078f,
    0.9998600091f,
    0.9998500105f
};

__device__ __forceinline__ float sigm(float x) {
    return __fdividef(1.0f, 1.0f + __expf(-x));
}

__global__ __launch_bounds__(TPB)
void ddm_kernel(const float* __restrict__ stim,
                const float* __restrict__ noise,
                const float* __restrict__ pa,
                const float* __restrict__ pz,
                const float* __restrict__ pg,
                const float* __restrict__ po,
                const float* __restrict__ pb,
                float* __restrict__ out,
                long long total_elems)      // n_trials * N_T
{
    const int t    = threadIdx.x;
    const int lane = t & 31;
    const int warp = t >> 5;

    const float a    = __ldg(pa);
    const float z    = __ldg(pz);
    const float g    = __ldg(pg);
    const float off  = __ldg(po);
    const float beta = __ldg(pb);

    const float e0     = z * a;
    const float cstim  = g * DT;
    const float cconst = off * DT + LEAK * e0 * DT;

    const bool active = (t < ACTIVE);

    // thread-level decay powers: Gd = D^(16t), F = D^(-16t)
    const float Gd    = __expf(LN_D16 * (float)t);
    const float F     = __expf(-LN_D16 * (float)t);
    const float nba   = -beta * a;
    const float tbase = (float)(t * CH) * TC;

    const size_t trial0 = (size_t)blockIdx.x * GTR;
    const size_t tofs   = (size_t)t * CH;

    __shared__ float sT[2][TPB / 32];   // parity double-buffered warp totals

    // ---- register double buffers for raw inputs ----
    float4 sb[2][4], nb[2][4];

    // prologue: issue loads for trial 0
    if (active) {
        const float4* sp = reinterpret_cast<const float4*>(stim  + trial0 * N_T + tofs);
        const float4* np = reinterpret_cast<const float4*>(noise + trial0 * N_T + tofs);
        #pragma unroll
        for (int q = 0; q < 4; q++) sb[0][q] = __ldcs(sp + q);
        #pragma unroll
        for (int q = 0; q < 4; q++) nb[0][q] = __ldcs(np + q);
    }

    #pragma unroll
    for (int i = 0; i < GTR; i++) {
        const int cur = i & 1;

        // issue next trial's loads before touching current data (overlap)
        if (i + 1 < GTR && active) {
            const size_t nb_base = (trial0 + i + 1) * N_T + tofs;
            const float4* sp = reinterpret_cast<const float4*>(stim  + nb_base);
            const float4* np = reinterpret_cast<const float4*>(noise + nb_base);
            #pragma unroll
            for (int q = 0; q < 4; q++) sb[cur ^ 1][q] = __ldcs(sp + q);
            #pragma unroll
            for (int q = 0; q < 4; q++) nb[cur ^ 1][q] = __ldcs(np + q);
        }

        // ---- local weighted prefix p[k] = sum_{j<=k} u[j] * D^-(j+1) ----
        float p[CH];
        if (active) {
            float dw  = 1.0f;     // DINV^(k+1), constant-folded per unrolled iter
            float acc = 0.0f;
            #pragma unroll
            for (int k = 0; k < CH; k++) {
                const float sv = (&sb[cur][k >> 2].x)[k & 3];
                const float nv = (&nb[cur][k >> 2].x)[k & 3];
                const float u  = fmaf(cstim, sv, fmaf(SQVDT, nv, cconst));
                dw *= DINV;
                acc = fmaf(u, dw, acc);
                p[k] = acc;
            }
        } else {
            #pragma unroll
            for (int k = 0; k < CH; k++) p[k] = 0.0f;
        }

        const float S = active ? F * p[CH - 1] : 0.0f;

        // ---- inclusive warp add-scan ----
        float si = S;
        #pragma unroll
        for (int d = 1; d < 32; d <<= 1) {
            const float o = __shfl_up_sync(0xffffffffu, si, d);
            if (lane >= d) si += o;
        }

        if (lane == 31) sT[cur][warp] = si;
        __syncthreads();

        float E = si - S;                 // exclusive prefix
        #pragma unroll
        for (int w = 0; w < TPB / 32; w++)
            if (w < warp) E += sT[cur][w];

        if (active) {
            const float basev = e0 + E;
            const size_t obase = (trial0 + i) * N_T + tofs;
            float* dvout = out + obase;
            float* h1out = out + (size_t)total_elems + obase;
            float* h0out = out + 2 * (size_t)total_elems + obase;

            // compute + store per 4-element group (low live-register pressure)
            #pragma unroll
            for (int q = 0; q < 4; q++) {
                float dvv[4], h1v[4], h0v[4];
                #pragma unroll
                for (int j = 0; j < 4; j++) {
                    const int   k     = q * 4 + j;
                    const float pprev = (k == 0) ? 0.0f : p[k - 1];
                    const float inner = fmaf(F, pprev, basev);
                    const float e   = Gd * (DPOW[k] * inner);
                    const float urg = tbase + (float)k * TC;
                    const float dv  = fmaf(urg, e - e0, e0);
                    dvv[j] = dv;
                    h1v[j] = sigm(fmaf(beta, dv, nba));   // sigmoid(beta*(dv-a))
                    h0v[j] = sigm(-beta * dv);            // sigmoid(-beta*dv)
                }
                __stcs(reinterpret_cast<float4*>(dvout) + q,
                       make_float4(dvv[0], dvv[1], dvv[2], dvv[3]));
                __stcs(reinterpret_cast<float4*>(h1out) + q,
                       make_float4(h1v[0], h1v[1], h1v[2], h1v[3]));
                __stcs(reinterpret_cast<float4*>(h0out) + q,
                       make_float4(h0v[0], h0v[1], h0v[2], h0v[3]));
            }
        }
    }
}

extern "C" void kernel_launch(void* const* d_in, const int* in_sizes, int n_in,
                              void* d_out, int out_size)
{
    const float* stim  = (const float*)d_in[0];
    const float* noise = (const float*)d_in[1];
    const float* pa    = (const float*)d_in[2];
    const float* pz    = (const float*)d_in[3];
    const float* pg    = (const float*)d_in[4];
    const float* po    = (const float*)d_in[5];
    const float* pb    = (const float*)d_in[6];
    float* out = (float*)d_out;

    const long long total = in_sizes[0];          // n_trials * N_T
    const int n_trials = (int)(total / N_T);
    const int n_blocks = (n_trials + GTR - 1) / GTR;   // 2048: single wave

    ddm_kernel<<<n_blocks, TPB>>>(stim, noise, pa, pz, pg, po, pb, out, total);
}

// round 7
// speedup vs baseline: 1.2834x; 1.1746x over previous
#include <cuda_runtime.h>

// SoftBoundDDM_RT: 4096 trials x 2000-step leaky-DDM recurrence + soft bounds.
// One block (512 thr) per trial; CH=4 timesteps per thread => every global
// load/store is a warp-contiguous 512B float4 access (perfect coalescing,
// no L1 wavefront inflation).
// Linear recurrence solved as a weighted prefix SUM:
//   e[T] = D^T * ( e0 + sum_{i<T} u[i] * D^-(i+1) ),  D = 0.99999
// (weights bounded by D^-2000 = 1.0202 -> perfectly conditioned).

constexpr int   N_T    = 2000;
constexpr int   CH     = 4;           // timesteps per thread (one float4)
constexpr int   TPB    = 512;         // 500 active threads (500*4 = 2000)
constexpr int   ACTIVE = 500;
constexpr int   NWARP  = TPB / 32;    // 16
constexpr float DT     = 0.001f;
constexpr float LEAK   = 0.01f;
constexpr float TC     = 0.01f;       // TIME_CONSTANT
constexpr float DECAY  = 1.0f - LEAK * DT;             // 0.99999
constexpr float DINV   = 1.0f / DECAY;
constexpr float LN_D4  = -4.0000200002e-5f;            // 4 * ln(0.99999)
constexpr float SQVDT  = 0.03162277660168379332f;      // sqrt(VARIANCE*DT)

// D^k for k=0..3 (immediates)
constexpr float DP0 = 1.0f;
constexpr float DP1 = 0.99999f;
constexpr float DP2 = 0.9999800001f;
constexpr float DP3 = 0.9999700003f;

__device__ __forceinline__ float sigm(float x) {
    return __fdividef(1.0f, 1.0f + __expf(-x));
}

__global__ __launch_bounds__(TPB, 3)
void ddm_kernel(const float* __restrict__ stim,
                const float* __restrict__ noise,
                const float* __restrict__ pa,
                const float* __restrict__ pz,
                const float* __restrict__ pg,
                const float* __restrict__ po,
                const float* __restrict__ pb,
                float* __restrict__ out,
                long long total_elems)      // n_trials * N_T
{
    const int t    = threadIdx.x;
    const int lane = t & 31;
    const int warp = t >> 5;

    const bool  active = (t < ACTIVE);
    const size_t base  = (size_t)blockIdx.x * N_T + (size_t)t * CH;

    // ---- issue both loads immediately (latency hidden under setup math) ----
    float4 s4 = make_float4(0.f, 0.f, 0.f, 0.f);
    float4 n4 = make_float4(0.f, 0.f, 0.f, 0.f);
    if (active) {
        s4 = __ldcs(reinterpret_cast<const float4*>(stim  + base));
        n4 = __ldcs(reinterpret_cast<const float4*>(noise + base));
    }

    const float a    = __ldg(pa);
    const float z    = __ldg(pz);
    const float g    = __ldg(pg);
    const float off  = __ldg(po);
    const float beta = __ldg(pb);

    const float e0     = z * a;
    const float cstim  = g * DT;
    const float cconst = off * DT + LEAK * e0 * DT;
    const float nba    = -beta * a;

    // thread-level decay powers: Gd = D^(4t), F = D^(-4t)
    const float Gd    = __expf(LN_D4 * (float)t);
    const float F     = __expf(-LN_D4 * (float)t);
    const float tbase = (float)(t * CH) * TC;

    // ---- local weighted prefix p[k] = sum_{j<=k} u[j] * D^-(j+1) ----
    float p0, p1, p2, p3;
    {
        const float u0 = fmaf(cstim, s4.x, fmaf(SQVDT, n4.x, cconst));
        const float u1 = fmaf(cstim, s4.y, fmaf(SQVDT, n4.y, cconst));
        const float u2 = fmaf(cstim, s4.z, fmaf(SQVDT, n4.z, cconst));
        const float u3 = fmaf(cstim, s4.w, fmaf(SQVDT, n4.w, cconst));
        p0 = u0 * (DINV);
        p1 = fmaf(u1, DINV * DINV, p0);
        p2 = fmaf(u2, DINV * DINV * DINV, p1);
        p3 = fmaf(u3, DINV * DINV * DINV * DINV, p2);
    }

    const float S = active ? F * p3 : 0.0f;

    // ---- inclusive warp add-scan ----
    float si = S;
    #pragma unroll
    for (int d = 1; d < 32; d <<= 1) {
        const float o = __shfl_up_sync(0xffffffffu, si, d);
        if (lane >= d) si += o;
    }

    __shared__ float sT[NWARP];
    if (lane == 31) sT[warp] = si;
    __syncthreads();

    float E = si - S;                 // exclusive prefix within warp
    #pragma unroll
    for (int w = 0; w < NWARP; w++)
        if (w < warp) E += sT[w];

    if (!active) return;

    // ---- outputs for the 4 timesteps ----
    const float basev = e0 + E;       // e0 + weighted sum of all earlier steps

    const float i0 = basev;                 // inner for k=0 (pprev = 0)
    const float i1 = fmaf(F, p0, basev);
    const float i2 = fmaf(F, p1, basev);
    const float i3 = fmaf(F, p2, basev);

    const float ev0 = Gd * (DP0 * i0);
    const float ev1 = Gd * (DP1 * i1);
    const float ev2 = Gd * (DP2 * i2);
    const float ev3 = Gd * (DP3 * i3);

    const float dv0 = fmaf(tbase + 0.0f * TC, ev0 - e0, e0);
    const float dv1 = fmaf(tbase + 1.0f * TC, ev1 - e0, e0);
    const float dv2 = fmaf(tbase + 2.0f * TC, ev2 - e0, e0);
    const float dv3 = fmaf(tbase + 3.0f * TC, ev3 - e0, e0);

    float* dvout = out + base;
    float* h1out = out + (size_t)total_elems + base;
    float* h0out = out + 2 * (size_t)total_elems + base;

    __stcs(reinterpret_cast<float4*>(dvout), make_float4(dv0, dv1, dv2, dv3));
    __stcs(reinterpret_cast<float4*>(h1out),
           make_float4(sigm(fmaf(beta, dv0, nba)), sigm(fmaf(beta, dv1, nba)),
                       sigm(fmaf(beta, dv2, nba)), sigm(fmaf(beta, dv3, nba))));
    __stcs(reinterpret_cast<float4*>(h0out),
           make_float4(sigm(-beta * dv0), sigm(-beta * dv1),
                       sigm(-beta * dv2), sigm(-beta * dv3)));
}

extern "C" void kernel_launch(void* const* d_in, const int* in_sizes, int n_in,
                              void* d_out, int out_size)
{
    const float* stim  = (const float*)d_in[0];
    const float* noise = (const float*)d_in[1];
    const float* pa    = (const float*)d_in[2];
    const float* pz    = (const float*)d_in[3];
    const float* pg    = (const float*)d_in[4];
    const float* po    = (const float*)d_in[5];
    const float* pb    = (const float*)d_in[6];
    float* out = (float*)d_out;

    const long long total = in_sizes[0];          // n_trials * N_T
    const int n_trials = (int)(total / N_T);

    ddm_kernel<<<n_trials, TPB>>>(stim, noise, pa, pz, pg, po, pb, out, total);
}

// round 8
// speedup vs baseline: 1.2945x; 1.0087x over previous
#include <cuda_runtime.h>

// SoftBoundDDM_RT: 4096 trials x 2000-step leaky-DDM recurrence + soft bounds.
// One WARP per trial, 16 rounds of 128 contiguous elements; no __syncthreads,
// no shared memory. Only cross-round dependency is a single FADD carry.
// Linear recurrence solved as a weighted prefix SUM:
//   e[T] = D^T * ( e0 + sum_{i<T} u[i] * D^-(i+1) ),  D = 0.99999
// (weights bounded by D^-2000 = 1.0202 -> perfectly conditioned).

constexpr int   N_T    = 2000;
constexpr int   TPB    = 128;         // 4 warps = 4 trials per block
constexpr int   WPB    = TPB / 32;
constexpr int   ROUNDS = 16;          // 15 full 128-elem rounds + 80-elem tail
constexpr float DT     = 0.001f;
constexpr float LEAK   = 0.01f;
constexpr float TC     = 0.01f;       // TIME_CONSTANT
constexpr float DECAY  = 1.0f - LEAK * DT;             // 0.99999
constexpr float DINV   = 1.0f / DECAY;
constexpr float LN_D   = -1.0000050000333e-5f;         // ln(0.99999)
constexpr float SQVDT  = 0.03162277660168379332f;      // sqrt(VARIANCE*DT)
constexpr float D128   = 0.99872081245862f;            // DECAY^128
constexpr float DI128  = 1.00128082595776f;            // DECAY^-128

// D^k for k=0..3 (immediates)
constexpr float DP1 = 0.99999f;
constexpr float DP2 = 0.9999800001f;
constexpr float DP3 = 0.9999700003f;

__device__ __forceinline__ float sigm(float x) {
    return __fdividef(1.0f, 1.0f + __expf(-x));
}

__global__ __launch_bounds__(TPB, 8)
void ddm_kernel(const float* __restrict__ stim,
                const float* __restrict__ noise,
                const float* __restrict__ pa,
                const float* __restrict__ pz,
                const float* __restrict__ pg,
                const float* __restrict__ po,
                const float* __restrict__ pb,
                float* __restrict__ out,
                long long total_elems,      // n_trials * N_T
                int n_trials)
{
    const int lane  = threadIdx.x & 31;
    const int warp  = threadIdx.x >> 5;
    const int trial = blockIdx.x * WPB + warp;
    if (trial >= n_trials) return;

    const float a    = __ldg(pa);
    const float z    = __ldg(pz);
    const float g    = __ldg(pg);
    const float off  = __ldg(po);
    const float beta = __ldg(pb);

    const float e0     = z * a;
    const float cstim  = g * DT;
    const float cconst = off * DT + LEAK * e0 * DT;
    const float nba    = -beta * a;

    // per-lane decay powers at pos0 = lane*4:  Gd = D^pos, F = D^-pos
    const int   pos0 = lane * 4;
    float Gd = __expf(LN_D * (float)pos0);
    float F  = __expf(-LN_D * (float)pos0);

    const size_t tb = (size_t)trial * N_T;
    const float* sp = stim  + tb;
    const float* np = noise + tb;
    float* dvout = out + tb;
    float* h1out = out + (size_t)total_elems + tb;
    float* h0out = out + 2 * (size_t)total_elems + tb;

    float eR = e0;                    // e0 + weighted sum of all prior rounds

    #pragma unroll
    for (int r = 0; r < ROUNDS; r++) {
        const int pos   = r * 128 + pos0;
        const bool live = (r < ROUNDS - 1) || (lane < 20);   // tail: 80 elems

        float4 s4 = make_float4(0.f, 0.f, 0.f, 0.f);
        float4 n4 = make_float4(0.f, 0.f, 0.f, 0.f);
        if (live) {
            s4 = __ldcs(reinterpret_cast<const float4*>(sp + pos));
            n4 = __ldcs(reinterpret_cast<const float4*>(np + pos));
        }

        // u and local weighted prefix q_k = sum_{j<=k} u_j * DINV^(j+1)
        const float u0 = fmaf(cstim, s4.x, fmaf(SQVDT, n4.x, cconst));
        const float u1 = fmaf(cstim, s4.y, fmaf(SQVDT, n4.y, cconst));
        const float u2 = fmaf(cstim, s4.z, fmaf(SQVDT, n4.z, cconst));
        const float u3 = fmaf(cstim, s4.w, fmaf(SQVDT, n4.w, cconst));
        const float q0 = u0 * DINV;
        const float q1 = fmaf(u1, DINV * DINV, q0);
        const float q2 = fmaf(u2, DINV * DINV * DINV, q1);
        const float q3 = fmaf(u3, DINV * DINV * DINV * DINV, q2);

        const float c = F * q3;       // this lane's chunk total (global weight)

        // inclusive warp add-scan (independent of carry eR)
        float si = c;
        #pragma unroll
        for (int d = 1; d < 32; d <<= 1) {
            const float o = __shfl_up_sync(0xffffffffu, si, d);
            if (lane >= d) si += o;
        }
        const float ex  = si - c;                          // exclusive prefix
        const float tot = __shfl_sync(0xffffffffu, si, 31);

        const float basev = eR + ex;   // e0 + full weighted prefix before pos

        // evidence / dv / sigmoids for the 4 elements
        const float i0 = basev;
        const float i1 = fmaf(F, q0, basev);
        const float i2 = fmaf(F, q1, basev);
        const float i3 = fmaf(F, q2, basev);

        const float ev0 = Gd * i0;
        const float ev1 = Gd * (DP1 * i1);
        const float ev2 = Gd * (DP2 * i2);
        const float ev3 = Gd * (DP3 * i3);

        const float fp  = (float)pos;
        const float dv0 = fmaf(fp * TC,          ev0 - e0, e0);
        const float dv1 = fmaf((fp + 1.f) * TC,  ev1 - e0, e0);
        const float dv2 = fmaf((fp + 2.f) * TC,  ev2 - e0, e0);
        const float dv3 = fmaf((fp + 3.f) * TC,  ev3 - e0, e0);

        if (live) {
            __stcs(reinterpret_cast<float4*>(dvout + pos),
                   make_float4(dv0, dv1, dv2, dv3));
            __stcs(reinterpret_cast<float4*>(h1out + pos),
                   make_float4(sigm(fmaf(beta, dv0, nba)), sigm(fmaf(beta, dv1, nba)),
                               sigm(fmaf(beta, dv2, nba)), sigm(fmaf(beta, dv3, nba))));
            __stcs(reinterpret_cast<float4*>(h0out + pos),
                   make_float4(sigm(-beta * dv0), sigm(-beta * dv1),
                               sigm(-beta * dv2), sigm(-beta * dv3)));
        }

        eR += tot;                    // the ONLY cross-round dependency
        F  *= DI128;                  // advance lane decay powers by 128 steps
        Gd *= D128;
    }
}

extern "C" void kernel_launch(void* const* d_in, const int* in_sizes, int n_in,
                              void* d_out, int out_size)
{
    const float* stim  = (const float*)d_in[0];
    const float* noise = (const float*)d_in[1];
    const float* pa    = (const float*)d_in[2];
    const float* pz    = (const float*)d_in[3];
    const float* pg    = (const float*)d_in[4];
    const float* po    = (const float*)d_in[5];
    const float* pb    = (const float*)d_in[6];
    float* out = (float*)d_out;

    const long long total = in_sizes[0];          // n_trials * N_T
    const int n_trials = (int)(total / N_T);
    const int n_blocks = (n_trials + WPB - 1) / WPB;   // 1024

    ddm_kernel<<<n_blocks, TPB>>>(stim, noise, pa, pz, pg, po, pb, out, total, n_trials);
}

// round 9
// speedup vs baseline: 1.3781x; 1.0645x over previous
#include <cuda_runtime.h>

// SoftBoundDDM_RT: 4096 trials x 2000-step leaky-DDM recurrence + soft bounds.
// One WARP per trial, 16 rounds of 128 contiguous elements; no __syncthreads,
// no shared memory. 1-round software prefetch hides DRAM latency; sigmoids via
// tanh.approx.f32 (1 MUFU instead of EX2+RCP) halve XU-pipe pressure.
// Linear recurrence solved as a weighted prefix SUM:
//   e[T] = D^T * ( e0 + sum_{i<T} u[i] * D^-(i+1) ),  D = 0.99999.

constexpr int   N_T    = 2000;
constexpr int   TPB    = 128;         // 4 warps = 4 trials per block
constexpr int   WPB    = TPB / 32;
constexpr int   ROUNDS = 16;          // 15 full 128-elem rounds + 80-elem tail
constexpr float DT     = 0.001f;
constexpr float LEAK   = 0.01f;
constexpr float TC     = 0.01f;       // TIME_CONSTANT
constexpr float DECAY  = 1.0f - LEAK * DT;             // 0.99999
constexpr float DINV   = 1.0f / DECAY;
constexpr float LN_D   = -1.0000050000333e-5f;         // ln(0.99999)
constexpr float SQVDT  = 0.03162277660168379332f;      // sqrt(VARIANCE*DT)
constexpr float D128   = 0.99872081245862f;            // DECAY^128
constexpr float DI128  = 1.00128082595776f;            // DECAY^-128

// D^k for k=0..3 (immediates)
constexpr float DP1 = 0.99999f;
constexpr float DP2 = 0.9999800001f;
constexpr float DP3 = 0.9999700003f;

__device__ __forceinline__ float tanh_fast(float x) {
    float y;
    asm("tanh.approx.f32 %0, %1;" : "=f"(y) : "f"(x));
    return y;
}

__global__ __launch_bounds__(TPB, 8)
void ddm_kernel(const float* __restrict__ stim,
                const float* __restrict__ noise,
                const float* __restrict__ pa,
                const float* __restrict__ pz,
                const float* __restrict__ pg,
                const float* __restrict__ po,
                const float* __restrict__ pb,
                float* __restrict__ out,
                long long total_elems,      // n_trials * N_T
                int n_trials)
{
    const int lane  = threadIdx.x & 31;
    const int warp  = threadIdx.x >> 5;
    const int trial = blockIdx.x * WPB + warp;
    if (trial >= n_trials) return;

    const float a    = __ldg(pa);
    const float z    = __ldg(pz);
    const float g    = __ldg(pg);
    const float off  = __ldg(po);
    const float beta = __ldg(pb);

    const float e0     = z * a;
    const float cstim  = g * DT;
    const float cconst = off * DT + LEAK * e0 * DT;
    const float hb     = 0.5f * beta;         // sigmoid(x)=0.5+0.5*tanh(x/2)
    const float hba    = hb * a;

    // per-lane decay powers at pos0 = lane*4:  Gd = D^pos, F = D^-pos
    const int   pos0 = lane * 4;
    float Gd = __expf(LN_D * (float)pos0);
    float F  = __expf(-LN_D * (float)pos0);

    const size_t tb = (size_t)trial * N_T;
    const float* sp = stim  + tb;
    const float* np = noise + tb;
    float* dvout = out + tb;
    float* h1out = out + (size_t)total_elems + tb;
    float* h0out = out + 2 * (size_t)total_elems + tb;

    float eR = e0;                    // e0 + weighted sum of all prior rounds

    // ---- prologue: prefetch round 0 ----
    float4 sA = make_float4(0.f, 0.f, 0.f, 0.f);
    float4 nA = make_float4(0.f, 0.f, 0.f, 0.f);
    sA = __ldcs(reinterpret_cast<const float4*>(sp + pos0));
    nA = __ldcs(reinterpret_cast<const float4*>(np + pos0));

    #pragma unroll
    for (int r = 0; r < ROUNDS; r++) {
        const int  pos  = r * 128 + pos0;
        const bool live = (r < ROUNDS - 1) || (lane < 20);   // tail: 80 elems

        // ---- prefetch round r+1 BEFORE consuming round r ----
        float4 sB = make_float4(0.f, 0.f, 0.f, 0.f);
        float4 nB = make_float4(0.f, 0.f, 0.f, 0.f);
        if (r + 1 < ROUNDS) {
            const bool liveN = (r + 1 < ROUNDS - 1) || (lane < 20);
            if (liveN) {
                sB = __ldcs(reinterpret_cast<const float4*>(sp + pos + 128));
                nB = __ldcs(reinterpret_cast<const float4*>(np + pos + 128));
            }
        }

        // u and local weighted prefix q_k = sum_{j<=k} u_j * DINV^(j+1)
        const float u0 = fmaf(cstim, sA.x, fmaf(SQVDT, nA.x, cconst));
        const float u1 = fmaf(cstim, sA.y, fmaf(SQVDT, nA.y, cconst));
        const float u2 = fmaf(cstim, sA.z, fmaf(SQVDT, nA.z, cconst));
        const float u3 = fmaf(cstim, sA.w, fmaf(SQVDT, nA.w, cconst));
        const float q0 = u0 * DINV;
        const float q1 = fmaf(u1, DINV * DINV, q0);
        const float q2 = fmaf(u2, DINV * DINV * DINV, q1);
        const float q3 = fmaf(u3, DINV * DINV * DINV * DINV, q2);

        const float c = live ? F * q3 : 0.0f;   // lane chunk total (global wt)

        // inclusive warp add-scan (independent of carry eR)
        float si = c;
        #pragma unroll
        for (int d = 1; d < 32; d <<= 1) {
            const float o = __shfl_up_sync(0xffffffffu, si, d);
            if (lane >= d) si += o;
        }
        const float ex  = si - c;                          // exclusive prefix
        const float tot = __shfl_sync(0xffffffffu, si, 31);

        const float basev = eR + ex;   // e0 + full weighted prefix before pos

        // evidence / dv / sigmoids for the 4 elements
        const float i0 = basev;
        const float i1 = fmaf(F, q0, basev);
        const float i2 = fmaf(F, q1, basev);
        const float i3 = fmaf(F, q2, basev);

        const float ev0 = Gd * i0;
        const float ev1 = Gd * (DP1 * i1);
        const float ev2 = Gd * (DP2 * i2);
        const float ev3 = Gd * (DP3 * i3);

        const float fp  = (float)pos;
        const float dv0 = fmaf(fp * TC,          ev0 - e0, e0);
        const float dv1 = fmaf((fp + 1.f) * TC,  ev1 - e0, e0);
        const float dv2 = fmaf((fp + 2.f) * TC,  ev2 - e0, e0);
        const float dv3 = fmaf((fp + 3.f) * TC,  ev3 - e0, e0);

        if (live) {
            __stcs(reinterpret_cast<float4*>(dvout + pos),
                   make_float4(dv0, dv1, dv2, dv3));
            // h1 = 0.5 + 0.5*tanh(hb*dv - hba)
            const float t10 = tanh_fast(fmaf(hb, dv0, -hba));
            const float t11 = tanh_fast(fmaf(hb, dv1, -hba));
            const float t12 = tanh_fast(fmaf(hb, dv2, -hba));
            const float t13 = tanh_fast(fmaf(hb, dv3, -hba));
            __stcs(reinterpret_cast<float4*>(h1out + pos),
                   make_float4(fmaf(0.5f, t10, 0.5f), fmaf(0.5f, t11, 0.5f),
                               fmaf(0.5f, t12, 0.5f), fmaf(0.5f, t13, 0.5f)));
            // h0 = 0.5 - 0.5*tanh(hb*dv)
            const float t00 = tanh_fast(hb * dv0);
            const float t01 = tanh_fast(hb * dv1);
            const float t02 = tanh_fast(hb * dv2);
            const float t03 = tanh_fast(hb * dv3);
            __stcs(reinterpret_cast<float4*>(h0out + pos),
                   make_float4(fmaf(-0.5f, t00, 0.5f), fmaf(-0.5f, t01, 0.5f),
                               fmaf(-0.5f, t02, 0.5f), fmaf(-0.5f, t03, 0.5f)));
        }

        eR += tot;                    // the ONLY cross-round dependency
        F  *= DI128;                  // advance lane decay powers by 128 steps
        Gd *= D128;

        sA = sB;                      // rotate prefetch buffers
        nA = nB;
    }
}

extern "C" void kernel_launch(void* const* d_in, const int* in_sizes, int n_in,
                              void* d_out, int out_size)
{
    const float* stim  = (const float*)d_in[0];
    const float* noise = (const float*)d_in[1];
    const float* pa    = (const float*)d_in[2];
    const float* pz    = (const float*)d_in[3];
    const float* pg    = (const float*)d_in[4];
    const float* po    = (const float*)d_in[5];
    const float* pb    = (const float*)d_in[6];
    float* out = (float*)d_out;

    const long long total = in_sizes[0];          // n_trials * N_T
    const int n_trials = (int)(total / N_T);
    const int n_blocks = (n_trials + WPB - 1) / WPB;   // 1024

    ddm_kernel<<<n_blocks, TPB>>>(stim, noise, pa, pz, pg, po, pb, out, total, n_trials);
}